// round 2
// baseline (speedup 1.0000x reference)
#include <cuda_runtime.h>

#define N_NODES 50000
#define N_EDGES 600000
#define D 128
#define TM 64   // rows per block in layer kernel

// -------- scratch (static device globals; no allocation allowed) --------
__device__ float g_bufA[(size_t)N_NODES * D];
__device__ float g_bufB[(size_t)N_NODES * D];
__device__ float g_agg [(size_t)N_NODES * D];
__device__ float g_invdeg[N_NODES];
__device__ int   g_deg[N_NODES];
__device__ int   g_off[N_NODES + 1];
__device__ int   g_cursor[N_NODES];
__device__ int   g_csr_src[N_EDGES];

// -------- small utility kernels --------
__global__ void zero_deg_kernel() {
    int i = blockIdx.x * blockDim.x + threadIdx.x;
    if (i < N_NODES) g_deg[i] = 0;
}

__global__ void hist_kernel(const int* __restrict__ dst) {
    int e = blockIdx.x * blockDim.x + threadIdx.x;
    if (e < N_EDGES) atomicAdd(&g_deg[dst[e]], 1);
}

__global__ void invdeg_kernel() {
    int i = blockIdx.x * blockDim.x + threadIdx.x;
    if (i < N_NODES) {
        int d = g_deg[i];
        g_invdeg[i] = 1.0f / (float)(d > 1 ? d : 1);
    }
}

// single-block exclusive scan over g_deg -> g_off (N_NODES+1 entries)
__global__ void scan_kernel() {
    __shared__ int warp_sums[32];
    __shared__ int s_carry;
    int tid = threadIdx.x;
    if (tid == 0) s_carry = 0;
    __syncthreads();
    for (int base = 0; base < N_NODES; base += 1024) {
        int i = base + tid;
        int v = (i < N_NODES) ? g_deg[i] : 0;
        // inclusive warp scan
        int x = v;
        #pragma unroll
        for (int o = 1; o < 32; o <<= 1) {
            int y = __shfl_up_sync(0xFFFFFFFFu, x, o);
            if ((tid & 31) >= o) x += y;
        }
        if ((tid & 31) == 31) warp_sums[tid >> 5] = x;
        __syncthreads();
        if (tid < 32) {
            int w = warp_sums[tid];
            #pragma unroll
            for (int o = 1; o < 32; o <<= 1) {
                int y = __shfl_up_sync(0xFFFFFFFFu, w, o);
                if (tid >= o) w += y;
            }
            warp_sums[tid] = w;
        }
        __syncthreads();
        int warp_prefix = (tid >= 32) ? warp_sums[(tid >> 5) - 1] : 0;
        int incl = x + warp_prefix;
        int carry = s_carry;
        if (i < N_NODES) g_off[i] = carry + incl - v;   // exclusive
        __syncthreads();
        if (tid == 1023) s_carry = carry + incl;
        __syncthreads();
    }
    if (tid == 0) g_off[N_NODES] = s_carry;
}

__global__ void cursor_init_kernel() {
    int i = blockIdx.x * blockDim.x + threadIdx.x;
    if (i < N_NODES) g_cursor[i] = g_off[i];
}

__global__ void fill_csr_kernel(const int* __restrict__ src,
                                const int* __restrict__ dst) {
    int e = blockIdx.x * blockDim.x + threadIdx.x;
    if (e < N_EDGES) {
        int d   = dst[e];
        int pos = atomicAdd(&g_cursor[d], 1);
        g_csr_src[pos] = src[e];
    }
}

// -------- gather aggregation: one warp per node, writes scaled agg --------
__global__ void gather_agg_kernel(const float* __restrict__ h) {
    int gtid = blockIdx.x * blockDim.x + threadIdx.x;
    int node = gtid >> 5;
    int lane = gtid & 31;
    if (node >= N_NODES) return;
    int beg = g_off[node];
    int end = g_off[node + 1];
    float4 s = make_float4(0.f, 0.f, 0.f, 0.f);
    for (int e = beg; e < end; ++e) {
        int sidx = g_csr_src[e];                       // broadcast across warp
        float4 v = ((const float4*)(h + (size_t)sidx * D))[lane];
        s.x += v.x; s.y += v.y; s.z += v.z; s.w += v.w;
    }
    float inv = g_invdeg[node];
    s.x *= inv; s.y *= inv; s.z *= inv; s.w *= inv;
    ((float4*)(g_agg + (size_t)node * D))[lane] = s;
}

// -------- fused layer: h_out = relu(agg@Wl + bl + h_in@Wr) --------
// smem: Wl[128x128], Wr[128x128], A[TMx128], H[TMx128] = 192 KB
__global__ void layer_kernel(const float* __restrict__ h_in,
                             float* __restrict__ h_out,
                             const float* __restrict__ Wl,
                             const float* __restrict__ bl,
                             const float* __restrict__ Wr) {
    extern __shared__ float sm[];
    float* Wl_s = sm;                 // D*D
    float* Wr_s = sm + D * D;         // D*D
    float* A_s  = sm + 2 * D * D;     // TM*D
    float* H_s  = A_s + TM * D;       // TM*D

    int tid  = threadIdx.x;
    int row0 = blockIdx.x * TM;

    // load weights (coalesced float4)
    for (int i = tid; i < D * D / 4; i += blockDim.x) {
        ((float4*)Wl_s)[i] = ((const float4*)Wl)[i];
        ((float4*)Wr_s)[i] = ((const float4*)Wr)[i];
    }
    // load A (already inv-deg scaled) and H tiles
    for (int i = tid; i < TM * D / 4; i += blockDim.x) {
        int r  = i / (D / 4);
        int c  = i % (D / 4);
        int gr = row0 + r;
        float4 a  = make_float4(0.f, 0.f, 0.f, 0.f);
        float4 h4 = make_float4(0.f, 0.f, 0.f, 0.f);
        if (gr < N_NODES) {
            a  = ((const float4*)(g_agg + (size_t)gr * D))[c];
            h4 = ((const float4*)(h_in + (size_t)gr * D))[c];
        }
        ((float4*)A_s)[i] = a;
        ((float4*)H_s)[i] = h4;
    }
    __syncthreads();

    int colg = tid & 31;   // cols colg*4 .. +3
    int rowg = tid >> 5;   // rows rowg*8 .. +7

    float acc[8][4];
    float4 b4 = ((const float4*)bl)[colg];
    #pragma unroll
    for (int i = 0; i < 8; i++) {
        acc[i][0] = b4.x; acc[i][1] = b4.y; acc[i][2] = b4.z; acc[i][3] = b4.w;
    }

    #pragma unroll 4
    for (int k = 0; k < D; k++) {
        float4 wl = ((const float4*)(Wl_s + k * D))[colg];
        float4 wr = ((const float4*)(Wr_s + k * D))[colg];
        #pragma unroll
        for (int i = 0; i < 8; i++) {
            float a = A_s[(rowg * 8 + i) * D + k];
            float h = H_s[(rowg * 8 + i) * D + k];
            acc[i][0] += a * wl.x; acc[i][1] += a * wl.y;
            acc[i][2] += a * wl.z; acc[i][3] += a * wl.w;
            acc[i][0] += h * wr.x; acc[i][1] += h * wr.y;
            acc[i][2] += h * wr.z; acc[i][3] += h * wr.w;
        }
    }

    #pragma unroll
    for (int i = 0; i < 8; i++) {
        int gr = row0 + rowg * 8 + i;
        if (gr < N_NODES) {
            float4 o;
            o.x = fmaxf(acc[i][0], 0.f);
            o.y = fmaxf(acc[i][1], 0.f);
            o.z = fmaxf(acc[i][2], 0.f);
            o.w = fmaxf(acc[i][3], 0.f);
            ((float4*)(h_out + (size_t)gr * D))[colg] = o;
        }
    }
}

// -------- output: out[i] = dot(h[i], Wout) + b_out --------
__global__ void out_kernel(const float* __restrict__ h,
                           const float* __restrict__ Wout,
                           const float* __restrict__ bout,
                           float* __restrict__ out) {
    int gtid = blockIdx.x * blockDim.x + threadIdx.x;
    int node = gtid >> 5;
    int lane = gtid & 31;
    if (node >= N_NODES) return;
    float4 hv = ((const float4*)(h + (size_t)node * D))[lane];
    float4 wv = ((const float4*)Wout)[lane];
    float s = hv.x * wv.x + hv.y * wv.y + hv.z * wv.z + hv.w * wv.w;
    #pragma unroll
    for (int o = 16; o > 0; o >>= 1)
        s += __shfl_xor_sync(0xFFFFFFFFu, s, o);
    if (lane == 0) out[node] = s + bout[0];
}

extern "C" void kernel_launch(void* const* d_in, const int* in_sizes, int n_in,
                              void* d_out, int out_size) {
    const float* x    = (const float*)d_in[0];
    const int*   ei   = (const int*)d_in[1];     // int32: JAX x64 disabled downcasts int64
    const int*   src  = ei;
    const int*   dst  = ei + N_EDGES;
    const float* Wl   = (const float*)d_in[2];
    const float* bl   = (const float*)d_in[3];
    const float* Wr   = (const float*)d_in[4];
    const float* Wout = (const float*)d_in[5];
    const float* bout = (const float*)d_in[6];
    float*       out  = (float*)d_out;

    float* bufA; cudaGetSymbolAddress((void**)&bufA, g_bufA);
    float* bufB; cudaGetSymbolAddress((void**)&bufB, g_bufB);

    const int smem_bytes = (2 * D * D + 2 * TM * D) * (int)sizeof(float); // 196608
    cudaFuncSetAttribute(layer_kernel, cudaFuncAttributeMaxDynamicSharedMemorySize,
                         smem_bytes);

    const int EB = (N_EDGES + 255) / 256;
    const int NB = (N_NODES + 255) / 256;
    const int WB = (N_NODES * 32 + 255) / 256;   // warp-per-node grids
    const int LB = (N_NODES + TM - 1) / TM;      // layer kernel blocks

    // build CSR (counting sort by dst)
    zero_deg_kernel<<<NB, 256>>>();
    hist_kernel<<<EB, 256>>>(dst);
    invdeg_kernel<<<NB, 256>>>();
    scan_kernel<<<1, 1024>>>();
    cursor_init_kernel<<<NB, 256>>>();
    fill_csr_kernel<<<EB, 256>>>(src, dst);

    // layer 0: x -> bufA
    gather_agg_kernel<<<WB, 256>>>(x);
    layer_kernel<<<LB, 256, smem_bytes>>>(x, bufA, Wl, bl, Wr);

    // layer 1: bufA -> bufB
    gather_agg_kernel<<<WB, 256>>>(bufA);
    layer_kernel<<<LB, 256, smem_bytes>>>(bufA, bufB, Wl + D * D, bl + D, Wr + D * D);

    // layer 2: bufB -> bufA
    gather_agg_kernel<<<WB, 256>>>(bufB);
    layer_kernel<<<LB, 256, smem_bytes>>>(bufB, bufA, Wl + 2 * D * D, bl + 2 * D,
                                          Wr + 2 * D * D);

    // output head
    out_kernel<<<WB, 256>>>(bufA, Wout, bout, out);
}

// round 6
// speedup vs baseline: 1.7057x; 1.7057x over previous
#include <cuda_runtime.h>
#include <cuda_bf16.h>
#include <cstdint>

#define N_NODES 50000
#define N_EDGES 600000
#define D 128
#define PADK 136            // bf16 elements per smem tile row (272B: conflict-free)

// ---------------- scratch (static device globals) ----------------
__device__ float g_bufA[(size_t)N_NODES * D];
__device__ float g_bufB[(size_t)N_NODES * D];
__device__ __nv_bfloat16 g_agg_hi[(size_t)N_NODES * D];
__device__ __nv_bfloat16 g_agg_lo[(size_t)N_NODES * D];
__device__ __nv_bfloat16 g_hA[(size_t)N_NODES * D];
__device__ __nv_bfloat16 g_lA[(size_t)N_NODES * D];
__device__ __nv_bfloat16 g_hB[(size_t)N_NODES * D];
__device__ __nv_bfloat16 g_lB[(size_t)N_NODES * D];
__device__ __nv_bfloat16 g_Wls[3 * 2 * D * D];   // [layer][hi/lo][n][k]
__device__ __nv_bfloat16 g_Wrs[3 * 2 * D * D];
__device__ float g_invdeg[N_NODES];
__device__ int   g_deg[N_NODES];
__device__ int   g_off[N_NODES + 1];
__device__ int   g_cursor[N_NODES];
__device__ int   g_csr_src[N_EDGES];
__device__ int   g_bsum[256];

// ---------------- CSR build ----------------
__global__ void zero_deg_kernel() {
    int i = blockIdx.x * blockDim.x + threadIdx.x;
    if (i < N_NODES) g_deg[i] = 0;
}
__global__ void hist_kernel(const int* __restrict__ dst) {
    int e = blockIdx.x * blockDim.x + threadIdx.x;
    if (e < N_EDGES) atomicAdd(&g_deg[dst[e]], 1);
}
__global__ void scan1_kernel() {
    __shared__ int wsum[8];
    int t = threadIdx.x;
    int i = blockIdx.x * 256 + t;
    int v = (i < N_NODES) ? g_deg[i] : 0;
    int x = v;
    #pragma unroll
    for (int o = 1; o < 32; o <<= 1) {
        int y = __shfl_up_sync(0xFFFFFFFFu, x, o);
        if ((t & 31) >= o) x += y;
    }
    if ((t & 31) == 31) wsum[t >> 5] = x;
    __syncthreads();
    if (t < 32) {
        int w = (t < 8) ? wsum[t] : 0;
        #pragma unroll
        for (int o = 1; o < 8; o <<= 1) {
            int y = __shfl_up_sync(0xFFFFFFFFu, w, o);
            if (t >= o) w += y;
        }
        if (t < 8) wsum[t] = w;
    }
    __syncthreads();
    int wp = (t >= 32) ? wsum[(t >> 5) - 1] : 0;
    if (i < N_NODES) g_off[i] = x - v + wp;
    if (t == 0) g_bsum[blockIdx.x] = wsum[7];
}
__global__ void scan2_kernel(int nblk) {
    __shared__ int wsum[8];
    int t = threadIdx.x;
    int v = (t < nblk) ? g_bsum[t] : 0;
    int x = v;
    #pragma unroll
    for (int o = 1; o < 32; o <<= 1) {
        int y = __shfl_up_sync(0xFFFFFFFFu, x, o);
        if ((t & 31) >= o) x += y;
    }
    if ((t & 31) == 31) wsum[t >> 5] = x;
    __syncthreads();
    if (t < 32) {
        int w = (t < 8) ? wsum[t] : 0;
        #pragma unroll
        for (int o = 1; o < 8; o <<= 1) {
            int y = __shfl_up_sync(0xFFFFFFFFu, w, o);
            if (t >= o) w += y;
        }
        if (t < 8) wsum[t] = w;
    }
    __syncthreads();
    int wp = (t >= 32) ? wsum[(t >> 5) - 1] : 0;
    g_bsum[t] = x - v + wp;
    if (t == 0) g_off[N_NODES] = wsum[7];
}
__global__ void scan3_kernel() {
    int b = blockIdx.x;
    int i = b * 256 + threadIdx.x;
    if (i < N_NODES) {
        int off = g_off[i] + g_bsum[b];
        g_off[i] = off;
        g_cursor[i] = off;
        int d = g_deg[i];
        g_invdeg[i] = 1.0f / (float)(d > 1 ? d : 1);
    }
}
__global__ void fill_csr_kernel(const int* __restrict__ src, const int* __restrict__ dst) {
    int e = blockIdx.x * blockDim.x + threadIdx.x;
    if (e < N_EDGES) {
        int pos = atomicAdd(&g_cursor[dst[e]], 1);
        g_csr_src[pos] = src[e];
    }
}

// ---------------- bf16 split helpers ----------------
// W[layer][k][n] fp32 -> [layer][hi/lo][n][k] bf16
__global__ void split_w_kernel(const float* __restrict__ Wl, const float* __restrict__ Wr) {
    int idx = blockIdx.x * blockDim.x + threadIdx.x;
    if (idx >= 3 * D * D) return;
    int layer = idx / (D * D);
    int rem   = idx % (D * D);
    int k = rem / D, n = rem % D;
    size_t dsthi = (size_t)layer * 2 * D * D + (size_t)n * D + k;
    size_t dstlo = dsthi + D * D;
    {
        float w = Wl[idx];
        __nv_bfloat16 hi = __float2bfloat16(w);
        g_Wls[dsthi] = hi;
        g_Wls[dstlo] = __float2bfloat16(w - __bfloat162float(hi));
    }
    {
        float w = Wr[idx];
        __nv_bfloat16 hi = __float2bfloat16(w);
        g_Wrs[dsthi] = hi;
        g_Wrs[dstlo] = __float2bfloat16(w - __bfloat162float(hi));
    }
}
__global__ void split_x_kernel(const float* __restrict__ x) {
    size_t i = (size_t)blockIdx.x * blockDim.x + threadIdx.x;
    if (i >= (size_t)N_NODES * D / 4) return;
    float4 v = ((const float4*)x)[i];
    __nv_bfloat16 h0 = __float2bfloat16(v.x), h1 = __float2bfloat16(v.y);
    __nv_bfloat16 h2 = __float2bfloat16(v.z), h3 = __float2bfloat16(v.w);
    ushort4 hi, lo;
    hi.x = __bfloat16_as_ushort(h0); hi.y = __bfloat16_as_ushort(h1);
    hi.z = __bfloat16_as_ushort(h2); hi.w = __bfloat16_as_ushort(h3);
    lo.x = __bfloat16_as_ushort(__float2bfloat16(v.x - __bfloat162float(h0)));
    lo.y = __bfloat16_as_ushort(__float2bfloat16(v.y - __bfloat162float(h1)));
    lo.z = __bfloat16_as_ushort(__float2bfloat16(v.z - __bfloat162float(h2)));
    lo.w = __bfloat16_as_ushort(__float2bfloat16(v.w - __bfloat162float(h3)));
    ((ushort4*)g_hA)[i] = hi;
    ((ushort4*)g_lA)[i] = lo;
}

// ---------------- gather: warp per node, bf16 hi/lo split output ----------------
__global__ void gather_agg_kernel(const float* __restrict__ h) {
    int gtid = blockIdx.x * blockDim.x + threadIdx.x;
    int node = gtid >> 5;
    int lane = gtid & 31;
    if (node >= N_NODES) return;
    int beg = g_off[node];
    int end = g_off[node + 1];
    float4 s = make_float4(0.f, 0.f, 0.f, 0.f);
    for (int e = beg; e < end; ++e) {
        int sidx = g_csr_src[e];
        float4 v = ((const float4*)(h + (size_t)sidx * D))[lane];
        s.x += v.x; s.y += v.y; s.z += v.z; s.w += v.w;
    }
    float inv = g_invdeg[node];
    s.x *= inv; s.y *= inv; s.z *= inv; s.w *= inv;
    __nv_bfloat16 h0 = __float2bfloat16(s.x), h1 = __float2bfloat16(s.y);
    __nv_bfloat16 h2 = __float2bfloat16(s.z), h3 = __float2bfloat16(s.w);
    ushort4 hi, lo;
    hi.x = __bfloat16_as_ushort(h0); hi.y = __bfloat16_as_ushort(h1);
    hi.z = __bfloat16_as_ushort(h2); hi.w = __bfloat16_as_ushort(h3);
    lo.x = __bfloat16_as_ushort(__float2bfloat16(s.x - __bfloat162float(h0)));
    lo.y = __bfloat16_as_ushort(__float2bfloat16(s.y - __bfloat162float(h1)));
    lo.z = __bfloat16_as_ushort(__float2bfloat16(s.z - __bfloat162float(h2)));
    lo.w = __bfloat16_as_ushort(__float2bfloat16(s.w - __bfloat162float(h3)));
    ((ushort4*)(g_agg_hi + (size_t)node * D))[lane] = hi;
    ((ushort4*)(g_agg_lo + (size_t)node * D))[lane] = lo;
}

// ---------------- warp-MMA fused layer ----------------
#define MMA_BF16(c, a, b) \
    asm volatile("mma.sync.aligned.m16n8k16.row.col.f32.bf16.bf16.f32 " \
                 "{%0,%1,%2,%3}, {%4,%5,%6,%7}, {%8,%9}, {%0,%1,%2,%3};" \
                 : "+f"((c)[0]), "+f"((c)[1]), "+f"((c)[2]), "+f"((c)[3]) \
                 : "r"((a)[0]), "r"((a)[1]), "r"((a)[2]), "r"((a)[3]), \
                   "r"((b)[0]), "r"((b)[1]))

// D_tile[128x128] = ahi@Wl_hi + ahi@Wl_lo + alo@Wl_hi
//                 + hhi@Wr_hi + hhi@Wr_lo + hlo@Wr_hi,  fp32 regs; bias+relu epilogue.
__global__ void __launch_bounds__(256, 1) mma_layer_kernel(
    const __nv_bfloat16* __restrict__ ahi, const __nv_bfloat16* __restrict__ alo,
    const __nv_bfloat16* __restrict__ hhi, const __nv_bfloat16* __restrict__ hlo,
    const __nv_bfloat16* __restrict__ wl,   // [2][n][k]: hi then lo
    const __nv_bfloat16* __restrict__ wr,
    const float* __restrict__ bias,
    float* __restrict__ hout,
    __nv_bfloat16* __restrict__ ohi, __nv_bfloat16* __restrict__ olo)
{
    extern __shared__ __nv_bfloat16 sm[];
    __nv_bfloat16* XH = sm;                   // 128*PADK each
    __nv_bfloat16* XL = XH + 128 * PADK;
    __nv_bfloat16* WH = XL + 128 * PADK;
    __nv_bfloat16* WL = WH + 128 * PADK;
    float* bias_s = (float*)(WL + 128 * PADK);

    const int tid  = threadIdx.x;
    const int lane = tid & 31;
    const int wid  = tid >> 5;
    const int mw   = wid & 3;          // 0..3: 32-row strip
    const int nw   = wid >> 2;         // 0..1: 64-col strip
    const int g    = lane >> 2;        // 0..7
    const int t    = lane & 3;         // 0..3
    const int row0 = blockIdx.x * 128;

    if (tid < 128) bias_s[tid] = bias[tid];

    float acc[2][8][4];
    #pragma unroll
    for (int s = 0; s < 2; s++)
        #pragma unroll
        for (int j = 0; j < 8; j++)
            #pragma unroll
            for (int q = 0; q < 4; q++) acc[s][j][q] = 0.f;

    #pragma unroll 1
    for (int phase = 0; phase < 2; phase++) {
        const __nv_bfloat16* srcH = phase ? hhi : ahi;
        const __nv_bfloat16* srcL = phase ? hlo : alo;
        const __nv_bfloat16* srcW = phase ? wr  : wl;
        if (phase) __syncthreads();      // previous mainloop done before overwrite

        // stage tiles: X guarded by N_NODES, W unguarded
        #pragma unroll
        for (int v = tid; v < 2048; v += 256) {
            int r = v >> 4, c = v & 15;
            uint4 xh = make_uint4(0, 0, 0, 0), xl = make_uint4(0, 0, 0, 0);
            int gr = row0 + r;
            if (gr < N_NODES) {
                xh = *(const uint4*)(srcH + (size_t)gr * D + c * 8);
                xl = *(const uint4*)(srcL + (size_t)gr * D + c * 8);
            }
            *(uint4*)(XH + r * PADK + c * 8) = xh;
            *(uint4*)(XL + r * PADK + c * 8) = xl;
            *(uint4*)(WH + r * PADK + c * 8) = *(const uint4*)(srcW + r * D + c * 8);
            *(uint4*)(WL + r * PADK + c * 8) = *(const uint4*)(srcW + D * D + r * D + c * 8);
        }
        __syncthreads();

        #pragma unroll
        for (int kk = 0; kk < 8; kk++) {
            const int kw = kk * 16 + t * 2;    // bf16 element offset of a0/b0 pair
            uint32_t aH[2][4], aL[2][4];
            #pragma unroll
            for (int s = 0; s < 2; s++) {
                int r = mw * 32 + s * 16 + g;
                aH[s][0] = *(const uint32_t*)(XH + r * PADK + kw);
                aH[s][1] = *(const uint32_t*)(XH + (r + 8) * PADK + kw);
                aH[s][2] = *(const uint32_t*)(XH + r * PADK + kw + 8);
                aH[s][3] = *(const uint32_t*)(XH + (r + 8) * PADK + kw + 8);
                aL[s][0] = *(const uint32_t*)(XL + r * PADK + kw);
                aL[s][1] = *(const uint32_t*)(XL + (r + 8) * PADK + kw);
                aL[s][2] = *(const uint32_t*)(XL + r * PADK + kw + 8);
                aL[s][3] = *(const uint32_t*)(XL + (r + 8) * PADK + kw + 8);
            }
            #pragma unroll
            for (int j = 0; j < 8; j++) {
                int n = nw * 64 + j * 8 + g;
                uint32_t bH[2], bL[2];
                bH[0] = *(const uint32_t*)(WH + n * PADK + kw);
                bH[1] = *(const uint32_t*)(WH + n * PADK + kw + 8);
                bL[0] = *(const uint32_t*)(WL + n * PADK + kw);
                bL[1] = *(const uint32_t*)(WL + n * PADK + kw + 8);
                #pragma unroll
                for (int s = 0; s < 2; s++) {
                    MMA_BF16(acc[s][j], aH[s], bH);
                    MMA_BF16(acc[s][j], aH[s], bL);
                    MMA_BF16(acc[s][j], aL[s], bH);
                }
            }
        }
    }

    // epilogue: bias + relu; fp32 out + bf16 hi/lo split out
    #pragma unroll
    for (int s = 0; s < 2; s++) {
        #pragma unroll
        for (int j = 0; j < 8; j++) {
            int col = nw * 64 + j * 8 + t * 2;
            float b0 = bias_s[col], b1 = bias_s[col + 1];
            #pragma unroll
            for (int hf = 0; hf < 2; hf++) {
                int r = row0 + mw * 32 + s * 16 + g + hf * 8;
                if (r < N_NODES) {
                    float v0 = fmaxf(acc[s][j][hf * 2 + 0] + b0, 0.f);
                    float v1 = fmaxf(acc[s][j][hf * 2 + 1] + b1, 0.f);
                    size_t base = (size_t)r * D + col;
                    *(float2*)(hout + base) = make_float2(v0, v1);
                    __nv_bfloat16 q0 = __float2bfloat16(v0);
                    __nv_bfloat16 q1 = __float2bfloat16(v1);
                    __nv_bfloat162 hp, lp;
                    hp.x = q0; hp.y = q1;
                    lp.x = __float2bfloat16(v0 - __bfloat162float(q0));
                    lp.y = __float2bfloat16(v1 - __bfloat162float(q1));
                    *(__nv_bfloat162*)(ohi + base) = hp;
                    *(__nv_bfloat162*)(olo + base) = lp;
                }
            }
        }
    }
}

// ---------------- output head ----------------
__global__ void out_kernel(const float* __restrict__ h,
                           const float* __restrict__ Wout,
                           const float* __restrict__ bout,
                           float* __restrict__ out) {
    int gtid = blockIdx.x * blockDim.x + threadIdx.x;
    int node = gtid >> 5;
    int lane = gtid & 31;
    if (node >= N_NODES) return;
    float4 hv = ((const float4*)(h + (size_t)node * D))[lane];
    float4 wv = ((const float4*)Wout)[lane];
    float s = hv.x * wv.x + hv.y * wv.y + hv.z * wv.z + hv.w * wv.w;
    #pragma unroll
    for (int o = 16; o > 0; o >>= 1)
        s += __shfl_xor_sync(0xFFFFFFFFu, s, o);
    if (lane == 0) out[node] = s + bout[0];
}

extern "C" void kernel_launch(void* const* d_in, const int* in_sizes, int n_in,
                              void* d_out, int out_size) {
    const float* x    = (const float*)d_in[0];
    const int*   ei   = (const int*)d_in[1];   // int32 (JAX x64 disabled)
    const int*   src  = ei;
    const int*   dst  = ei + N_EDGES;
    const float* Wl   = (const float*)d_in[2];
    const float* bl   = (const float*)d_in[3];
    const float* Wr   = (const float*)d_in[4];
    const float* Wout = (const float*)d_in[5];
    const float* bout = (const float*)d_in[6];
    float*       out  = (float*)d_out;

    float* bufA; cudaGetSymbolAddress((void**)&bufA, g_bufA);
    float* bufB; cudaGetSymbolAddress((void**)&bufB, g_bufB);
    __nv_bfloat16* aggH; cudaGetSymbolAddress((void**)&aggH, g_agg_hi);
    __nv_bfloat16* aggL; cudaGetSymbolAddress((void**)&aggL, g_agg_lo);
    __nv_bfloat16* hA; cudaGetSymbolAddress((void**)&hA, g_hA);
    __nv_bfloat16* lA; cudaGetSymbolAddress((void**)&lA, g_lA);
    __nv_bfloat16* hB; cudaGetSymbolAddress((void**)&hB, g_hB);
    __nv_bfloat16* lB; cudaGetSymbolAddress((void**)&lB, g_lB);
    __nv_bfloat16* Wls; cudaGetSymbolAddress((void**)&Wls, g_Wls);
    __nv_bfloat16* Wrs; cudaGetSymbolAddress((void**)&Wrs, g_Wrs);

    const int LAYER_SMEM = 4 * 128 * PADK * 2 + 128 * 4;   // 139776 + 512
    cudaFuncSetAttribute(mma_layer_kernel, cudaFuncAttributeMaxDynamicSharedMemorySize,
                         LAYER_SMEM);

    const int EB = (N_EDGES + 255) / 256;
    const int NB = (N_NODES + 255) / 256;          // 196
    const int WB = (N_NODES * 32 + 255) / 256;
    const int LB = (N_NODES + 127) / 128;          // 391

    // CSR build
    zero_deg_kernel<<<NB, 256>>>();
    hist_kernel<<<EB, 256>>>(dst);
    scan1_kernel<<<NB, 256>>>();
    scan2_kernel<<<1, 256>>>(NB);
    scan3_kernel<<<NB, 256>>>();
    fill_csr_kernel<<<EB, 256>>>(src, dst);

    // bf16 splits of weights and input features
    split_w_kernel<<<(3 * D * D + 255) / 256, 256>>>(Wl, Wr);
    split_x_kernel<<<((N_NODES * D / 4) + 255) / 256, 256>>>(x);

    // layer 0: x -> bufA (+ hB/lB splits)
    gather_agg_kernel<<<WB, 256>>>(x);
    mma_layer_kernel<<<LB, 256, LAYER_SMEM>>>(aggH, aggL, hA, lA,
                                              Wls, Wrs, bl, bufA, hB, lB);
    // layer 1: bufA -> bufB (+ hA/lA)
    gather_agg_kernel<<<WB, 256>>>(bufA);
    mma_layer_kernel<<<LB, 256, LAYER_SMEM>>>(aggH, aggL, hB, lB,
                                              Wls + 2 * D * D, Wrs + 2 * D * D,
                                              bl + D, bufB, hA, lA);
    // layer 2: bufB -> bufA
    gather_agg_kernel<<<WB, 256>>>(bufB);
    mma_layer_kernel<<<LB, 256, LAYER_SMEM>>>(aggH, aggL, hA, lA,
                                              Wls + 4 * D * D, Wrs + 4 * D * D,
                                              bl + 2 * D, bufA, hB, lB);
    // head
    out_kernel<<<WB, 256>>>(bufA, Wout, bout, out);
}